// round 15
// baseline (speedup 1.0000x reference)
#include <cuda_runtime.h>
#include <cuda_fp16.h>
#include <cstdint>

#define NB   65536
#define SQ   9
#define DM   20
#define NH   4
#define DHD  5
#define DFF  512
#define EPSV 1e-5f

typedef unsigned long long u64;
typedef unsigned int u32;

// scratch: y = LN1(attn_out + x), fp32 (exact, needed for residual)
__device__ __align__(16) float g_y[(size_t)NB * SQ * DM];

// ---------------- mma helpers ----------------
__device__ __forceinline__ void mma16816(float* d,
                                         u32 a0, u32 a1, u32 a2, u32 a3,
                                         u32 b0, u32 b1) {
    asm volatile(
        "mma.sync.aligned.m16n8k16.row.col.f32.f16.f16.f32 "
        "{%0,%1,%2,%3}, {%4,%5,%6,%7}, {%8,%9}, {%0,%1,%2,%3};"
        : "+f"(d[0]), "+f"(d[1]), "+f"(d[2]), "+f"(d[3])
        : "r"(a0), "r"(a1), "r"(a2), "r"(a3), "r"(b0), "r"(b1));
}
__device__ __forceinline__ void mma1688(float* d, u32 a0, u32 a1, u32 b0) {
    asm volatile(
        "mma.sync.aligned.m16n8k8.row.col.f32.f16.f16.f32 "
        "{%0,%1,%2,%3}, {%4,%5}, {%6}, {%0,%1,%2,%3};"
        : "+f"(d[0]), "+f"(d[1]), "+f"(d[2]), "+f"(d[3])
        : "r"(a0), "r"(a1), "r"(b0));
}
__device__ __forceinline__ u32 cvt2(float x, float y) {
    __half2 hh = __floats2half2_rn(x, y);
    return *(u32*)&hh;
}
__device__ __forceinline__ u32 pack2relu(float x, float y) {
    __half2 hh = __floats2half2_rn(x, y);
    hh = __hmax2(hh, __float2half2_rn(0.f));
    return *(u32*)&hh;
}

// ======================================================================
// Kernel 1: attention + LN1, QKV/Wo via mma.sync (fp16), softmax fp32.
// (R14 champion, unchanged)
// ======================================================================
#define AT 288
#define GRID1 (NB / 32)   // 2048

#define A_WQKV 0
#define A_WO   3072
#define A_BQKV 4224
#define A_BO   4480
#define A_G1   4576
#define A_B1   4656
#define A_M    4736
#define A_U    32384
#define SMEM1  (A_U + 288 * 69 * 4)    // 111872

__global__ void __launch_bounds__(AT, 2) k_attn3(
    const float* __restrict__ X,
    const float* __restrict__ Wq, const float* __restrict__ bq,
    const float* __restrict__ Wk, const float* __restrict__ bk,
    const float* __restrict__ Wv, const float* __restrict__ bv,
    const float* __restrict__ Wo, const float* __restrict__ bo,
    const float* __restrict__ g1, const float* __restrict__ b1)
{
    extern __shared__ __align__(16) char sm1[];
    __half* sWqkv = (__half*)(sm1 + A_WQKV);
    __half* sWo   = (__half*)(sm1 + A_WO);
    float*  sBqkv = (float*)(sm1 + A_BQKV);
    float*  sBo   = (float*)(sm1 + A_BO);
    float*  sG1   = (float*)(sm1 + A_G1);
    float*  sB1   = (float*)(sm1 + A_B1);
    float*  sM    = (float*)(sm1 + A_M);
    float*  sQKV  = (float*)(sm1 + A_U);
    float*  stage = (float*)(sm1 + A_U);

    const int tid  = threadIdx.x;
    const int w    = tid >> 5;
    const int lane = tid & 31;
    const int r    = lane >> 2;
    const int c    = lane & 3;

    for (int i = tid; i < 64 * 24; i += AT) {
        const int n = i / 24, k = i - n * 24;
        float v = 0.f;
        if (k < DM) {
            if (n < 20)      v = Wq[k * DM + n];
            else if (n < 40) v = Wk[k * DM + n - 20];
            else if (n < 60) v = Wv[k * DM + n - 40];
        }
        sWqkv[n * 24 + k] = __float2half_rn(v);
    }
    for (int i = tid; i < 24 * 24; i += AT) {
        const int n = i / 24, k = i - n * 24;
        sWo[n * 24 + k] = __float2half_rn((n < DM && k < DM) ? Wo[k * DM + n] : 0.f);
    }
    if (tid < 64)
        sBqkv[tid] = (tid < 20) ? bq[tid]
                   : (tid < 40) ? bk[tid - 20]
                   : (tid < 60) ? bv[tid - 40] : 0.f;
    if (tid < 24) sBo[tid] = (tid < DM) ? bo[tid] : 0.f;
    if (tid < DM) { sG1[tid] = g1[tid]; sB1[tid] = b1[tid]; }

    const size_t rowbase = (size_t)blockIdx.x * AT;
    const size_t myrow   = rowbase + tid;

    float x[DM];
    {
        const float4* xr = (const float4*)(X + myrow * DM);
        #pragma unroll
        for (int i = 0; i < 5; i++) {
            float4 t = xr[i];
            x[4*i] = t.x; x[4*i+1] = t.y; x[4*i+2] = t.z; x[4*i+3] = t.w;
        }
    }
    __syncthreads();

    // ---- QKV GEMM ----
    {
        u32 a[2][6];
        #pragma unroll
        for (int m = 0; m < 2; m++) {
            const float* x0 = X + (rowbase + w * 32 + m * 16 + r) * DM;
            const float* x1 = x0 + 8 * DM;
            float2 p;
            p = *(const float2*)(x0 + 2 * c);     a[m][0] = cvt2(p.x, p.y);
            p = *(const float2*)(x1 + 2 * c);     a[m][1] = cvt2(p.x, p.y);
            p = *(const float2*)(x0 + 2 * c + 8); a[m][2] = cvt2(p.x, p.y);
            p = *(const float2*)(x1 + 2 * c + 8); a[m][3] = cvt2(p.x, p.y);
            if (c < 2) {
                p = *(const float2*)(x0 + 16 + 2 * c); a[m][4] = cvt2(p.x, p.y);
                p = *(const float2*)(x1 + 16 + 2 * c); a[m][5] = cvt2(p.x, p.y);
            } else {
                a[m][4] = a[m][5] = 0u;
            }
        }
        #pragma unroll
        for (int nt = 0; nt < 8; nt++) {
            const char* bb = (const char*)sWqkv + (nt * 8 + r) * 48 + c * 4;
            const u32 b0 = *(const u32*)bb;
            const u32 b1 = *(const u32*)(bb + 16);
            const u32 t0 = *(const u32*)(bb + 32);
            #pragma unroll
            for (int m = 0; m < 2; m++) {
                float d[4] = {0.f, 0.f, 0.f, 0.f};
                mma16816(d, a[m][0], a[m][1], a[m][2], a[m][3], b0, b1);
                mma1688(d, a[m][4], a[m][5], t0);
                const int C  = nt * 8 + 2 * c;
                const int R0 = w * 32 + m * 16 + r;
                sQKV[R0 * 69 + C]       = d[0] + sBqkv[C];
                sQKV[R0 * 69 + C + 1]   = d[1] + sBqkv[C + 1];
                sQKV[(R0+8) * 69 + C]     = d[2] + sBqkv[C];
                sQKV[(R0+8) * 69 + C + 1] = d[3] + sBqkv[C + 1];
            }
        }
    }
    __syncthreads();

    // ---- attention (fp32 scalar) ----
    {
        const int bl = tid / SQ;
        const int s  = tid - bl * SQ;
        float q[DM];
        #pragma unroll
        for (int d = 0; d < DM; d++) q[d] = sQKV[tid * 69 + d];

        #pragma unroll
        for (int h = 0; h < NH; h++) {
            float sc[SQ];
            float mx = -1e30f;
            #pragma unroll
            for (int j = 0; j < SQ; j++) {
                const float* kr = sQKV + (bl * SQ + j) * 69 + 20 + h * DHD;
                float a = 0.f;
                #pragma unroll
                for (int dh = 0; dh < DHD; dh++)
                    a = fmaf(q[h * DHD + dh], kr[dh], a);
                a *= (1.0f / 3.0f);
                sc[j] = a;
                mx = fmaxf(mx, a);
            }
            float den = 0.f;
            #pragma unroll
            for (int j = 0; j < SQ; j++) { sc[j] = __expf(sc[j] - mx); den += sc[j]; }
            const float inv = 1.0f / den;
            float ctx[DHD] = {0.f, 0.f, 0.f, 0.f, 0.f};
            #pragma unroll
            for (int j = 0; j < SQ; j++) {
                const float p = sc[j];
                const float* vr = sQKV + (bl * SQ + j) * 69 + 40 + h * DHD;
                #pragma unroll
                for (int dh = 0; dh < DHD; dh++)
                    ctx[dh] = fmaf(p, vr[dh], ctx[dh]);
            }
            #pragma unroll
            for (int dh = 0; dh < DHD; dh++) {
                const int f = h * 45 + dh * 9 + s;
                sM[(bl * SQ + f / 20) * 24 + (f % 20)] = ctx[dh] * inv;
            }
        }
        sM[tid * 24 + 20] = 0.f; sM[tid * 24 + 21] = 0.f;
        sM[tid * 24 + 22] = 0.f; sM[tid * 24 + 23] = 0.f;
    }
    __syncthreads();

    // ---- Wo GEMM ----
    {
        u32 a[2][6];
        #pragma unroll
        for (int m = 0; m < 2; m++) {
            const float* m0 = sM + (w * 32 + m * 16 + r) * 24;
            const float* m1 = m0 + 8 * 24;
            float2 p;
            p = *(const float2*)(m0 + 2 * c);      a[m][0] = cvt2(p.x, p.y);
            p = *(const float2*)(m1 + 2 * c);      a[m][1] = cvt2(p.x, p.y);
            p = *(const float2*)(m0 + 2 * c + 8);  a[m][2] = cvt2(p.x, p.y);
            p = *(const float2*)(m1 + 2 * c + 8);  a[m][3] = cvt2(p.x, p.y);
            p = *(const float2*)(m0 + 16 + 2 * c); a[m][4] = cvt2(p.x, p.y);
            p = *(const float2*)(m1 + 16 + 2 * c); a[m][5] = cvt2(p.x, p.y);
        }
        float* st = stage + w * (32 * 29);
        #pragma unroll
        for (int nt = 0; nt < 3; nt++) {
            const char* bb = (const char*)sWo + (nt * 8 + r) * 48 + c * 4;
            const u32 b0 = *(const u32*)bb;
            const u32 b1 = *(const u32*)(bb + 16);
            const u32 t0 = *(const u32*)(bb + 32);
            #pragma unroll
            for (int m = 0; m < 2; m++) {
                float d[4] = {0.f, 0.f, 0.f, 0.f};
                mma16816(d, a[m][0], a[m][1], a[m][2], a[m][3], b0, b1);
                mma1688(d, a[m][4], a[m][5], t0);
                const int C  = nt * 8 + 2 * c;
                const int R0 = m * 16 + r;
                st[R0 * 29 + C]       = d[0];
                st[R0 * 29 + C + 1]   = d[1];
                st[(R0+8) * 29 + C]     = d[2];
                st[(R0+8) * 29 + C + 1] = d[3];
            }
        }
    }
    __syncwarp();

    // ---- epilogue: attn_out + bo + x -> LN1 -> g_y ----
    {
        const float* ao = stage + w * (32 * 29) + lane * 29;
        float rr[DM];
        float mean = 0.f;
        #pragma unroll
        for (int d = 0; d < DM; d++) {
            rr[d] = ao[d] + sBo[d] + x[d];
            mean += rr[d];
        }
        mean *= (1.0f / 20.0f);
        float var = 0.f;
        #pragma unroll
        for (int d = 0; d < DM; d++) { const float t = rr[d] - mean; var = fmaf(t, t, var); }
        var *= (1.0f / 20.0f);
        const float rstd = rsqrtf(var + EPSV);

        float4* yo = (float4*)(g_y + myrow * DM);
        #pragma unroll
        for (int i = 0; i < 5; i++) {
            float4 t;
            t.x = (rr[4*i+0] - mean) * rstd * sG1[4*i+0] + sB1[4*i+0];
            t.y = (rr[4*i+1] - mean) * rstd * sG1[4*i+1] + sB1[4*i+1];
            t.z = (rr[4*i+2] - mean) * rstd * sG1[4*i+2] + sB1[4*i+2];
            t.w = (rr[4*i+3] - mean) * rstd * sG1[4*i+3] + sB1[4*i+3];
            yo[i] = t;
        }
    }
}

// ======================================================================
// Kernel 2: FFN via mma.sync — pure fp16, fp32 accumulate.
// Restructured: split-d1 interleave (GEMM2 group A overlaps GEMM1 group
// B), shuffle-based LN2 epilogue (no smem staging), 384 threads x 2
// blocks/SM (regs capped 85, smem 62KB/block).
// ======================================================================
#define FTHR    384
#define FWPB    12
#define PASSES  6
#define ROWS_PP (FWPB * 32)                         // 384 rows per pass
#define GRID2   (NB * SQ / (ROWS_PP * PASSES))     // 256

#define O_W1    0                       // [512 n][36 k] f16, rows 72B
#define O_W2    36864                   // [24 n][520 k] f16, rows 1040B
#define O_G2B2  61824                   // 20 + 20 f32
#define SMEMF   (O_G2B2 + 40 * 4)       // 61984

__global__ void __launch_bounds__(FTHR, 2) k_ffn4(
    const float* __restrict__ W1, const float* __restrict__ W2,
    const float* __restrict__ g2, const float* __restrict__ b2,
    float* __restrict__ Out)
{
    extern __shared__ __align__(16) char sm[];
    const int tid = threadIdx.x;

    for (int i = tid; i < DFF * 36; i += FTHR) {
        const int n = i / 36, k = i - n * 36;
        const float v = (k < DM) ? W1[k * DFF + n] : 0.f;
        *(__half*)(sm + O_W1 + n * 72 + k * 2) = __float2half_rn(v);
    }
    for (int i = tid; i < 24 * 520; i += FTHR) {
        const int n = i / 520, k = i - n * 520;
        const float v = (n < DM && k < DFF) ? W2[k * DM + n] : 0.f;
        *(__half*)(sm + O_W2 + n * 1040 + k * 2) = __float2half_rn(v);
    }
    float* sG2 = (float*)(sm + O_G2B2);
    float* sB2 = sG2 + 20;
    if (tid < DM) { sG2[tid] = g2[tid]; sB2[tid] = b2[tid]; }
    __syncthreads();

    const int w    = tid >> 5;
    const int lane = tid & 31;
    const int r    = lane >> 2;
    const int c    = lane & 3;

    // LN2 params for this thread's columns (col = nt2*8 + 2c; pad if >= 20)
    float2 gg[3], bb[3];
    #pragma unroll
    for (int nt2 = 0; nt2 < 3; nt2++) {
        const int col = nt2 * 8 + 2 * c;
        if (col < DM) {
            gg[nt2] = *(const float2*)(sG2 + col);
            bb[nt2] = *(const float2*)(sB2 + col);
        } else {
            gg[nt2] = make_float2(0.f, 0.f);
            bb[nt2] = make_float2(0.f, 0.f);
        }
    }

    #pragma unroll 1
    for (int pass = 0; pass < PASSES; pass++) {
        const size_t wbase = ((size_t)blockIdx.x * PASSES + pass) * (size_t)ROWS_PP
                           + (size_t)w * 32;

        // ---- y A-fragments (fp16), K padded 20 -> 32 ----
        u32 ah[2][6];
        #pragma unroll
        for (int m = 0; m < 2; m++) {
            const float* y0 = g_y + (wbase + m * 16 + r) * DM;
            const float* y1 = y0 + 8 * DM;
            float2 p;
            p = *(const float2*)(y0 + 2 * c);     ah[m][0] = cvt2(p.x, p.y);
            p = *(const float2*)(y1 + 2 * c);     ah[m][1] = cvt2(p.x, p.y);
            p = *(const float2*)(y0 + 2 * c + 8); ah[m][2] = cvt2(p.x, p.y);
            p = *(const float2*)(y1 + 2 * c + 8); ah[m][3] = cvt2(p.x, p.y);
            if (c < 2) {
                p = *(const float2*)(y0 + 16 + 2 * c); ah[m][4] = cvt2(p.x, p.y);
                p = *(const float2*)(y1 + 16 + 2 * c); ah[m][5] = cvt2(p.x, p.y);
            } else {
                ah[m][4] = ah[m][5] = 0u;
            }
        }

        float d2[3][2][4];
        #pragma unroll
        for (int n = 0; n < 3; n++)
            #pragma unroll
            for (int m = 0; m < 2; m++)
                #pragma unroll
                for (int i = 0; i < 4; i++) d2[n][m][i] = 0.f;

        #pragma unroll 1
        for (int ch = 0; ch < 16; ch++) {
            // Two half-chunks: group g covers hidden n [ch*32+g*16, +16).
            // GEMM2 of group 0 is independent of GEMM1 of group 1 -> ILP.
            #pragma unroll
            for (int g = 0; g < 2; g++) {
                float d1[2][2][4];
                #pragma unroll
                for (int n = 0; n < 2; n++)
                    #pragma unroll
                    for (int m = 0; m < 2; m++)
                        #pragma unroll
                        for (int i = 0; i < 4; i++) d1[n][m][i] = 0.f;

                #pragma unroll
                for (int nt = 0; nt < 2; nt++) {
                    const u32 boff = (u32)((ch * 32 + (g * 2 + nt) * 8 + r) * 72 + c * 4);
                    const u32 b0 = *(const u32*)(sm + O_W1 + boff);
                    const u32 b1 = *(const u32*)(sm + O_W1 + boff + 16);
                    const u32 t0 = *(const u32*)(sm + O_W1 + boff + 32);
                    #pragma unroll
                    for (int m = 0; m < 2; m++) {
                        mma16816(d1[nt][m], ah[m][0], ah[m][1], ah[m][2], ah[m][3], b0, b1);
                        mma1688(d1[nt][m], ah[m][4], ah[m][5], t0);
                    }
                }

                u32 fh[2][4];
                #pragma unroll
                for (int m = 0; m < 2; m++) {
                    fh[m][0] = pack2relu(d1[0][m][0], d1[0][m][1]);
                    fh[m][1] = pack2relu(d1[0][m][2], d1[0][m][3]);
                    fh[m][2] = pack2relu(d1[1][m][0], d1[1][m][1]);
                    fh[m][3] = pack2relu(d1[1][m][2], d1[1][m][3]);
                }
                #pragma unroll
                for (int nt2 = 0; nt2 < 3; nt2++) {
                    const u32 boff = (u32)((nt2 * 8 + r) * 1040
                                   + (ch * 32 + g * 16) * 2 + c * 4);
                    const u32 b0 = *(const u32*)(sm + O_W2 + boff);
                    const u32 b1 = *(const u32*)(sm + O_W2 + boff + 16);
                    #pragma unroll
                    for (int m = 0; m < 2; m++)
                        mma16816(d2[nt2][m], fh[m][0], fh[m][1], fh[m][2], fh[m][3], b0, b1);
                }
            }
        }

        // ---- shuffle-based epilogue: residual + LN2 -> Out ----
        #pragma unroll
        for (int m = 0; m < 2; m++) {
            #pragma unroll
            for (int h2 = 0; h2 < 2; h2++) {
                const size_t row = wbase + m * 16 + h2 * 8 + r;
                float rr[3][2];
                float s = 0.f, sq = 0.f;
                #pragma unroll
                for (int nt2 = 0; nt2 < 3; nt2++) {
                    const int col = nt2 * 8 + 2 * c;
                    if (col < DM) {
                        const float2 yv = *(const float2*)(g_y + row * DM + col);
                        const float a = yv.x + d2[nt2][m][h2 * 2 + 0];
                        const float b = yv.y + d2[nt2][m][h2 * 2 + 1];
                        rr[nt2][0] = a; rr[nt2][1] = b;
                        s += a + b;
                        sq = fmaf(a, a, sq); sq = fmaf(b, b, sq);
                    }
                }
                s  += __shfl_xor_sync(0xffffffffu, s, 1);
                s  += __shfl_xor_sync(0xffffffffu, s, 2);
                sq += __shfl_xor_sync(0xffffffffu, sq, 1);
                sq += __shfl_xor_sync(0xffffffffu, sq, 2);
                const float mean = s * (1.0f / 20.0f);
                const float var  = sq * (1.0f / 20.0f) - mean * mean;
                const float rstd = rsqrtf(var + EPSV);
                #pragma unroll
                for (int nt2 = 0; nt2 < 3; nt2++) {
                    const int col = nt2 * 8 + 2 * c;
                    if (col < DM) {
                        float2 o;
                        o.x = (rr[nt2][0] - mean) * rstd * gg[nt2].x + bb[nt2].x;
                        o.y = (rr[nt2][1] - mean) * rstd * gg[nt2].y + bb[nt2].y;
                        *(float2*)(Out + row * DM + col) = o;
                    }
                }
            }
        }
    }
}

// ======================================================================
// Launch
// ======================================================================
extern "C" void kernel_launch(void* const* d_in, const int* in_sizes, int n_in,
                              void* d_out, int out_size)
{
    (void)in_sizes; (void)n_in; (void)out_size;
    const float* X  = (const float*)d_in[0];
    const float* Wq = (const float*)d_in[1];
    const float* bq = (const float*)d_in[2];
    const float* Wk = (const float*)d_in[3];
    const float* bk = (const float*)d_in[4];
    const float* Wv = (const float*)d_in[5];
    const float* bv = (const float*)d_in[6];
    const float* Wo = (const float*)d_in[7];
    const float* bo = (const float*)d_in[8];
    const float* g1 = (const float*)d_in[9];
    const float* b1 = (const float*)d_in[10];
    const float* W1 = (const float*)d_in[11];
    const float* W2 = (const float*)d_in[12];
    const float* g2 = (const float*)d_in[13];
    const float* b2 = (const float*)d_in[14];
    float* Out = (float*)d_out;

    cudaFuncSetAttribute(k_attn3, cudaFuncAttributeMaxDynamicSharedMemorySize, SMEM1);
    cudaFuncSetAttribute(k_ffn4, cudaFuncAttributeMaxDynamicSharedMemorySize, SMEMF);

    k_attn3<<<GRID1, AT, SMEM1>>>(X, Wq, bq, Wk, bk, Wv, bv, Wo, bo, g1, b1);
    k_ffn4<<<GRID2, FTHR, SMEMF>>>(W1, W2, g2, b2, Out);
}